// round 17
// baseline (speedup 1.0000x reference)
#include <cuda_runtime.h>
#include <cstdint>

#define N_NODES 50000
#define N_EDGES 800000
#define DIM 128
#define HEADS 4
#define NEG_SLOPE 0.2f
#define LN_EPS 1e-5f

#define SCAN_BLK 256
#define N_SCAN_BLKS ((N_NODES + SCAN_BLK - 1) / SCAN_BLK)   // 196

// Scratch (device globals: no allocation allowed in kernel_launch)
__device__ __align__(256) float g_xl[N_NODES * DIM];   // 25.6 MB
__device__ __align__(256) float g_xr[N_NODES * DIM];   // 25.6 MB
__device__ int g_deg[N_NODES];
__device__ int g_off[N_NODES];
__device__ int g_cursor[N_NODES];
__device__ int g_bsum[N_SCAN_BLKS];
__device__ int g_csr_src[N_EDGES];
__device__ int g_is64;

__device__ __forceinline__ int load_idx(const void* raw, int pos, int is64) {
    return is64 ? (int)((const long long*)raw)[pos] : ((const int*)raw)[pos];
}

// f32x2 packed helpers (sm_103a FFMA2 — only reachable via PTX)
__device__ __forceinline__ unsigned long long pack_dup(float v) {
    unsigned long long r;
    asm("mov.b64 %0, {%1, %1};" : "=l"(r) : "f"(v));
    return r;
}
__device__ __forceinline__ void fma2(unsigned long long& acc,
                                     unsigned long long a, unsigned long long b) {
    asm("fma.rn.f32x2 %0, %1, %2, %0;" : "+l"(acc) : "l"(a), "l"(b));
}
__device__ __forceinline__ float2 unpack2(unsigned long long v) {
    float lo, hi;
    asm("mov.b64 {%0, %1}, %2;" : "=f"(lo), "=f"(hi) : "l"(v));
    return make_float2(lo, hi);
}

// ---------------------------------------------------------------------------
// CSR stream: dtype sniff + zero degree array.
// ---------------------------------------------------------------------------
__global__ void prep_kernel(const void* __restrict__ ei_raw) {
    int i = blockIdx.x * blockDim.x + threadIdx.x;
    if (i == 0) {
        const long long* e64 = (const long long*)ei_raw;
        int ok = 1;
        #pragma unroll
        for (int j = 0; j < 16; j++) {
            long long v = e64[j];
            if (v < 0 || v >= N_NODES) ok = 0;
        }
        g_is64 = ok;
    }
    int stride = gridDim.x * blockDim.x;
    for (int j = i; j < N_NODES; j += stride) g_deg[j] = 0;
}

// CSR stream: degree histogram
__global__ void hist_kernel(const void* __restrict__ ei_raw) {
    int is64 = g_is64;
    int i = blockIdx.x * blockDim.x + threadIdx.x;
    int stride = gridDim.x * blockDim.x;
    for (int e = i; e < N_EDGES; e += stride) {
        int d = load_idx(ei_raw, N_EDGES + e, is64);
        atomicAdd(&g_deg[d], 1);
    }
}

// CSR stream: per-block inclusive scan of deg chunk; block total to g_bsum.
__global__ void scan1_kernel() {
    __shared__ int sh[SCAN_BLK];
    int tid = threadIdx.x;
    int i = blockIdx.x * SCAN_BLK + tid;
    int v = (i < N_NODES) ? g_deg[i] : 0;
    sh[tid] = v;
    __syncthreads();
    #pragma unroll
    for (int o = 1; o < SCAN_BLK; o <<= 1) {
        int t = (tid >= o) ? sh[tid - o] : 0;
        __syncthreads();
        sh[tid] += t;
        __syncthreads();
    }
    if (i < N_NODES) g_off[i] = sh[tid];           // inclusive local
    if (tid == SCAN_BLK - 1) g_bsum[blockIdx.x] = sh[tid];
}

// CSR stream: finalize offsets (each block reduces its prefix of block totals)
__global__ void scan3_kernel() {
    __shared__ int sh[SCAN_BLK];
    int tid = threadIdx.x;
    int bid = blockIdx.x;
    sh[tid] = (tid < bid) ? g_bsum[tid] : 0;        // bid <= 196 <= SCAN_BLK
    __syncthreads();
    #pragma unroll
    for (int o = SCAN_BLK / 2; o > 0; o >>= 1) {
        if (tid < o) sh[tid] += sh[tid + o];
        __syncthreads();
    }
    int prefix = sh[0];
    int i = bid * SCAN_BLK + tid;
    if (i < N_NODES) {
        int excl = g_off[i] - g_deg[i] + prefix;
        g_off[i] = excl;
        g_cursor[i] = excl;
    }
}

// CSR stream: fill
__global__ void fill_kernel(const void* __restrict__ ei_raw) {
    int is64 = g_is64;
    int i = blockIdx.x * blockDim.x + threadIdx.x;
    int stride = gridDim.x * blockDim.x;
    for (int e = i; e < N_EDGES; e += stride) {
        int s = load_idx(ei_raw, e, is64);
        int d = load_idx(ei_raw, N_EDGES + e, is64);
        int pos = atomicAdd(&g_cursor[d], 1);
        g_csr_src[pos] = s;
    }
}

// ---------------------------------------------------------------------------
// GEMM stream: xl = x@W_l + b_l ; xr = x@W_r + b_r.
// NPW=6: W traffic per node -33% vs NPW=4 (R7 profile showed L1 = 78.9%),
// regs ~95 -> still 2 blocks/SM.
// ---------------------------------------------------------------------------
__global__ void __launch_bounds__(256, 2)
gemm_kernel(const float* __restrict__ x,
            const float* __restrict__ Wl, const float* __restrict__ bl,
            const float* __restrict__ Wr, const float* __restrict__ br) {
    const int lane = threadIdx.x & 31;
    const int warp = (blockIdx.x * blockDim.x + threadIdx.x) >> 5;
    const int nwarp = (gridDim.x * blockDim.x) >> 5;
    const int NPW = 6;

    float4 bl4 = ((const float4*)bl)[lane];
    float4 br4 = ((const float4*)br)[lane];

    for (int base = warp * NPW; base < N_NODES; base += nwarp * NPW) {
        float4 xv[NPW];
        #pragma unroll
        for (int i = 0; i < NPW; i++) {
            int n = base + i;
            xv[i] = (n < N_NODES) ? ((const float4*)(x + (size_t)n * DIM))[lane]
                                  : make_float4(0.f, 0.f, 0.f, 0.f);
        }
        unsigned long long al2[NPW][2], ar2[NPW][2];
        #pragma unroll
        for (int i = 0; i < NPW; i++) {
            al2[i][0] = 0ull; al2[i][1] = 0ull;
            ar2[i][0] = 0ull; ar2[i][1] = 0ull;
        }

        #pragma unroll
        for (int k4 = 0; k4 < DIM / 4; k4++) {
            #pragma unroll
            for (int c = 0; c < 4; c++) {
                const int k = k4 * 4 + c;
                ulonglong2 wl2 = ((const ulonglong2*)(Wl + (size_t)k * DIM))[lane];
                ulonglong2 wr2 = ((const ulonglong2*)(Wr + (size_t)k * DIM))[lane];
                #pragma unroll
                for (int i = 0; i < NPW; i++) {
                    float comp = (c == 0) ? xv[i].x : (c == 1) ? xv[i].y
                               : (c == 2) ? xv[i].z : xv[i].w;
                    float xk = __shfl_sync(0xffffffffu, comp, k4);
                    unsigned long long xk2 = pack_dup(xk);
                    fma2(al2[i][0], wl2.x, xk2);
                    fma2(al2[i][1], wl2.y, xk2);
                    fma2(ar2[i][0], wr2.x, xk2);
                    fma2(ar2[i][1], wr2.y, xk2);
                }
            }
        }

        #pragma unroll
        for (int i = 0; i < NPW; i++) {
            int n = base + i;
            if (n < N_NODES) {
                float2 l01 = unpack2(al2[i][0]);
                float2 l23 = unpack2(al2[i][1]);
                float2 r01 = unpack2(ar2[i][0]);
                float2 r23 = unpack2(ar2[i][1]);
                float4 ol = make_float4(l01.x + bl4.x, l01.y + bl4.y,
                                        l23.x + bl4.z, l23.y + bl4.w);
                float4 orr = make_float4(r01.x + br4.x, r01.y + br4.y,
                                         r23.x + br4.z, r23.y + br4.w);
                ((float4*)(g_xl + (size_t)n * DIM))[lane] = ol;
                ((float4*)(g_xr + (size_t)n * DIM))[lane] = orr;
            }
        }
    }
}

// ---------------------------------------------------------------------------
// join: fused per-dst softmax-gather + residual + LN.
// Quad-level PING-PONG software pipeline: load quad B(q+1) before computing
// quad A(q), so each quad's ~250-cycle L2 gather latency overlaps the
// previous quad's compute. Only the two gather buffers (8 float4) are live
// across the overlap (R12's register blow-up kept p[8]/w[8] live too).
// Node-ahead prefetch retained (4 nodes/warp at 1563 blocks).
// alpha = exp(e)/sum(exp(e)) equals the reference softmax (max cancels).
// ---------------------------------------------------------------------------
__device__ __forceinline__ float edge_logit(float4 a, float4 xr4, float4 at) {
    float vx = a.x + xr4.x; vx = vx > 0.f ? vx : NEG_SLOPE * vx;
    float vy = a.y + xr4.y; vy = vy > 0.f ? vy : NEG_SLOPE * vy;
    float vz = a.z + xr4.z; vz = vz > 0.f ? vz : NEG_SLOPE * vz;
    float vw = a.w + xr4.w; vw = vw > 0.f ? vw : NEG_SLOPE * vw;
    return vx * at.x + vy * at.y + vz * at.z + vw * at.w;
}

__global__ void fused_edge_kernel(const float* __restrict__ x,
                                  const float* __restrict__ att,
                                  const float* __restrict__ bias,
                                  const float* __restrict__ gamma,
                                  const float* __restrict__ beta,
                                  float* __restrict__ out) {
    const int lane = threadIdx.x & 31;
    const int warp = (blockIdx.x * blockDim.x + threadIdx.x) >> 5;
    const int nwarp = (gridDim.x * blockDim.x) >> 5;
    const unsigned FULL = 0xffffffffu;

    float4 at = ((const float4*)att)[lane];
    float4 bi = ((const float4*)bias)[lane];
    float4 ga = ((const float4*)gamma)[lane];
    float4 be = ((const float4*)beta)[lane];

    // prime the node-ahead prefetch
    int pf_beg = 0, pf_deg = 0, pf_src = 0;
    float4 pf_xr = make_float4(0.f, 0.f, 0.f, 0.f);
    if (warp < N_NODES) {
        pf_beg = g_off[warp];
        pf_deg = g_deg[warp];
        pf_xr = ((const float4*)(g_xr + (size_t)warp * DIM))[lane];
        pf_src = (lane < min(pf_deg, 32)) ? g_csr_src[pf_beg + lane] : 0;
    }

    for (int d = warp; d < N_NODES; d += nwarp) {
        const int beg = pf_beg;
        const int deg = pf_deg;
        const int src0 = pf_src;
        const float4 xr4 = pf_xr;

        int dn = d + nwarp;
        if (dn < N_NODES) {
            pf_beg = g_off[dn];
            pf_deg = g_deg[dn];
            pf_xr = ((const float4*)(g_xr + (size_t)dn * DIM))[lane];
            pf_src = (lane < min(pf_deg, 32)) ? g_csr_src[pf_beg + lane] : 0;
        }

        float4 accA = make_float4(0.f, 0.f, 0.f, 0.f);
        float4 accB = make_float4(0.f, 0.f, 0.f, 0.f);
        float denA = 0.f, denB = 0.f;

        for (int base = 0; base < deg; base += 32) {
            int cnt = min(32, deg - base);
            int my_src = (base == 0) ? src0
                        : ((lane < cnt) ? g_csr_src[beg + base + lane] : 0);

            int nq = cnt >> 2;   // full quads

            float4 A0, A1, A2, A3, B0, B1, B2, B3;

            // macro-free helpers via lambdas are not allowed in __global__;
            // use explicit code.
            #define LOAD_QUAD(R0, R1, R2, R3, qq)                                 \
                do {                                                              \
                    int _s0 = __shfl_sync(FULL, my_src, (qq) * 4 + 0);            \
                    int _s1 = __shfl_sync(FULL, my_src, (qq) * 4 + 1);            \
                    int _s2 = __shfl_sync(FULL, my_src, (qq) * 4 + 2);            \
                    int _s3 = __shfl_sync(FULL, my_src, (qq) * 4 + 3);            \
                    R0 = ((const float4*)(g_xl + (size_t)_s0 * DIM))[lane];       \
                    R1 = ((const float4*)(g_xl + (size_t)_s1 * DIM))[lane];       \
                    R2 = ((const float4*)(g_xl + (size_t)_s2 * DIM))[lane];       \
                    R3 = ((const float4*)(g_xl + (size_t)_s3 * DIM))[lane];       \
                } while (0)

            #define COMPUTE_QUAD(R0, R1, R2, R3)                                  \
                do {                                                              \
                    float _p0 = edge_logit(R0, xr4, at);                          \
                    float _p1 = edge_logit(R1, xr4, at);                          \
                    float _p2 = edge_logit(R2, xr4, at);                          \
                    float _p3 = edge_logit(R3, xr4, at);                          \
                    _Pragma("unroll")                                             \
                    for (int off = 4; off > 0; off >>= 1) {                       \
                        _p0 += __shfl_xor_sync(FULL, _p0, off);                   \
                        _p1 += __shfl_xor_sync(FULL, _p1, off);                   \
                        _p2 += __shfl_xor_sync(FULL, _p2, off);                   \
                        _p3 += __shfl_xor_sync(FULL, _p3, off);                   \
                    }                                                             \
                    float _w0 = __expf(_p0), _w1 = __expf(_p1);                   \
                    float _w2 = __expf(_p2), _w3 = __expf(_p3);                   \
                    denA += _w0 + _w1;                                            \
                    denB += _w2 + _w3;                                            \
                    accA.x += _w0 * R0.x + _w1 * R1.x;                            \
                    accA.y += _w0 * R0.y + _w1 * R1.y;                            \
                    accA.z += _w0 * R0.z + _w1 * R1.z;                            \
                    accA.w += _w0 * R0.w + _w1 * R1.w;                            \
                    accB.x += _w2 * R2.x + _w3 * R3.x;                            \
                    accB.y += _w2 * R2.y + _w3 * R3.y;                            \
                    accB.z += _w2 * R2.z + _w3 * R3.z;                            \
                    accB.w += _w2 * R2.w + _w3 * R3.w;                            \
                } while (0)

            int q = 0;
            if (nq > 0) LOAD_QUAD(A0, A1, A2, A3, 0);
            while (q + 2 <= nq) {
                LOAD_QUAD(B0, B1, B2, B3, q + 1);
                COMPUTE_QUAD(A0, A1, A2, A3);
                if (q + 2 < nq) LOAD_QUAD(A0, A1, A2, A3, q + 2);
                COMPUTE_QUAD(B0, B1, B2, B3);
                q += 2;
            }
            if (q < nq) COMPUTE_QUAD(A0, A1, A2, A3);

            #undef LOAD_QUAD
            #undef COMPUTE_QUAD

            // tail edges
            for (int j = nq * 4; j < cnt; j++) {
                int s = __shfl_sync(FULL, my_src, j);
                float4 a = ((const float4*)(g_xl + (size_t)s * DIM))[lane];
                float p = edge_logit(a, xr4, at);
                #pragma unroll
                for (int off = 4; off > 0; off >>= 1)
                    p += __shfl_xor_sync(FULL, p, off);
                float w = __expf(p);
                denA += w;
                accA.x += w * a.x;
                accA.y += w * a.y;
                accA.z += w * a.z;
                accA.w += w * a.w;
            }
        }

        float den = denA + denB;
        float4 acc = make_float4(accA.x + accB.x, accA.y + accB.y,
                                 accA.z + accB.z, accA.w + accB.w);
        float inv = (den > 0.f) ? __frcp_rn(den) : 0.f;

        float4 xv = ((const float4*)(x + (size_t)d * DIM))[lane];
        float4 o;
        o.x = acc.x * inv + bi.x + xv.x;
        o.y = acc.y * inv + bi.y + xv.y;
        o.z = acc.z * inv + bi.z + xv.z;
        o.w = acc.w * inv + bi.w + xv.w;

        float s = o.x + o.y + o.z + o.w;
        #pragma unroll
        for (int off = 16; off > 0; off >>= 1)
            s += __shfl_xor_sync(FULL, s, off);
        float mu = s * (1.0f / DIM);

        float dx = o.x - mu, dy = o.y - mu, dz = o.z - mu, dw = o.w - mu;
        float q2 = dx * dx + dy * dy + dz * dz + dw * dw;
        #pragma unroll
        for (int off = 16; off > 0; off >>= 1)
            q2 += __shfl_xor_sync(FULL, q2, off);
        float rs = rsqrtf(q2 * (1.0f / DIM) + LN_EPS);

        float4 r;
        r.x = dx * rs * ga.x + be.x;
        r.y = dy * rs * ga.y + be.y;
        r.z = dz * rs * ga.z + be.z;
        r.w = dw * rs * ga.w + be.w;
        ((float4*)(out + (size_t)d * DIM))[lane] = r;
    }
}

extern "C" void kernel_launch(void* const* d_in, const int* in_sizes, int n_in,
                              void* d_out, int out_size) {
    const float* x     = (const float*)d_in[0];
    const void*  ei    = d_in[1];
    const float* Wl    = (const float*)d_in[2];
    const float* bl    = (const float*)d_in[3];
    const float* Wr    = (const float*)d_in[4];
    const float* br    = (const float*)d_in[5];
    const float* att   = (const float*)d_in[6];
    const float* bias  = (const float*)d_in[7];
    const float* gamma = (const float*)d_in[8];
    const float* beta  = (const float*)d_in[9];
    float*       out   = (float*)d_out;

    // Lazily-created side streams/events (host handles only; no device mem).
    static cudaStream_t s_gemm = nullptr, s_csr = nullptr;
    static cudaEvent_t ev_fork = nullptr, ev_gemm = nullptr, ev_csr = nullptr;
    if (!s_gemm) {
        cudaStreamCreateWithFlags(&s_gemm, cudaStreamNonBlocking);
        cudaStreamCreateWithFlags(&s_csr, cudaStreamNonBlocking);
        cudaEventCreateWithFlags(&ev_fork, cudaEventDisableTiming);
        cudaEventCreateWithFlags(&ev_gemm, cudaEventDisableTiming);
        cudaEventCreateWithFlags(&ev_csr, cudaEventDisableTiming);
    }

    // Fork from the default stream (capture-safe event fork/join pattern).
    cudaEventRecord(ev_fork, 0);
    cudaStreamWaitEvent(s_gemm, ev_fork, 0);
    cudaStreamWaitEvent(s_csr, ev_fork, 0);

    // GEMM branch (independent of CSR build)
    // 50000 / (6 nodes/warp * 8 warps/block) = 1042 blocks
    gemm_kernel<<<1042, 256, 0, s_gemm>>>(x, Wl, bl, Wr, br);

    // CSR branch, runs concurrently with the GEMM
    prep_kernel<<<256, 256, 0, s_csr>>>(ei);
    hist_kernel<<<1024, 256, 0, s_csr>>>(ei);
    scan1_kernel<<<N_SCAN_BLKS, SCAN_BLK, 0, s_csr>>>();
    scan3_kernel<<<N_SCAN_BLKS, SCAN_BLK, 0, s_csr>>>();
    fill_kernel<<<1024, 256, 0, s_csr>>>(ei);

    // Join both branches back onto the default stream.
    cudaEventRecord(ev_gemm, s_gemm);
    cudaEventRecord(ev_csr, s_csr);
    cudaStreamWaitEvent(0, ev_gemm, 0);
    cudaStreamWaitEvent(0, ev_csr, 0);

    // 1563 blocks x 8 warps = 12504 warps -> ~4 nodes/warp (prefetch active)
    fused_edge_kernel<<<1563, 256>>>(x, att, bias, gamma, beta, out);
}